// round 1
// baseline (speedup 1.0000x reference)
#include <cuda_runtime.h>
#include <math.h>

// ---------------- problem constants ----------------
#define NB   16      // b*m images for global path
#define D    256
#define NH   8
#define HD   32
#define NTOK 98      // m*w*w = 2*7*7
#define NWIN 512     // b*gx*gy
#define SEH  64
#define H1   56
#define H2   28
#define H3   14
#define MROWS 50176  // NWIN*NTOK

// ---------------- scratch (device globals, no allocs) ----------------
__device__ float g_xg0[NB*D*H1*H1];
__device__ float g_y  [NB*D*H1*H1];
__device__ float g_z  [NB*D*H1*H1];
__device__ float g_xg1[NB*D*H2*H2];
__device__ float g_xg2[NB*D*H3*H3];
__device__ float g_smean[NB*D];
__device__ float g_svec [NB*D];
__device__ float g_gout [8*4*NTOK*D];
__device__ float g_qglob[8*NTOK*D];
__device__ float g_kv   [(size_t)NWIN*NTOK*2*D];
__device__ float g_biasb[NH*NTOK*NTOK];
__device__ float g_aout [(size_t)NWIN*NTOK*D];

__device__ __forceinline__ float gelu_f(float v){
    return 0.5f*v*(1.0f+erff(v*0.70710678118654752440f));
}

// x-layout row offset for (win, token): identical for input x and final output
__device__ __forceinline__ long xrow_off(int r){
    int win=r/NTOK, i=r%NTOK;
    int b=win>>6, gx=(win>>3)&7, gy=win&7;
    int m=i/49, rr=i%49, w1=rr/7, w2=rr%7;
    return (((((long)(b*2+m)*8+gx)*8+gy)*7+w1)*7+w2)*256;
}

// ---------------- 1. rearrange x -> (b*m, d, 56, 56) ----------------
__global__ void k_rearrange(const float* __restrict__ x){
    int o=blockIdx.x*blockDim.x+threadIdx.x;
    if(o>=NB*D*H1*H1) return;
    int Wp=o%H1; int t=o/H1;
    int Hp=t%H1; t/=H1;
    int c=t%D;   int n=t/D;
    int b=n>>1, m=n&1;
    int gx=Hp/7, w1=Hp%7;
    int gy=Wp/7, w2=Wp%7;
    long off=(((((long)(b*2+m)*8+gx)*8+gy)*7+w1)*7+w2)*256 + c;
    g_xg0[o]=x[off];
}

// ---------------- 2. depthwise 3x3 conv (pad 1) + exact GELU ----------------
__global__ void k_dwconv_gelu(const float* __restrict__ in, const float* __restrict__ dw,
                              float* __restrict__ out, int HW){
    int o=blockIdx.x*blockDim.x+threadIdx.x;
    int total=NB*D*HW*HW;
    if(o>=total) return;
    int wx=o%HW; int t=o/HW;
    int hy=t%HW; t/=HW;          // t = n*D + c
    int c=t%D;
    const float* ip = in + (long)t*HW*HW;
    const float* wp = dw + c*9;
    float acc=0.f;
    #pragma unroll
    for(int kh=0;kh<3;kh++){
        int hh=hy+kh-1;
        if(hh<0||hh>=HW) continue;
        #pragma unroll
        for(int kw=0;kw<3;kw++){
            int ww=wx+kw-1;
            if(ww<0||ww>=HW) continue;
            acc += ip[hh*HW+ww]*wp[kh*3+kw];
        }
    }
    out[o]=gelu_f(acc);
}

// ---------------- 3. mean over HW per (n,c) ----------------
__global__ void k_hwmean(const float* __restrict__ y, float* __restrict__ sm, int HW){
    int nc=blockIdx.x;
    const float* p = y + (long)nc*HW*HW;
    float s=0.f;
    for(int i=threadIdx.x;i<HW*HW;i+=blockDim.x) s+=p[i];
    __shared__ float red[256];
    red[threadIdx.x]=s; __syncthreads();
    for(int st=128;st>0;st>>=1){
        if(threadIdx.x<st) red[threadIdx.x]+=red[threadIdx.x+st];
        __syncthreads();
    }
    if(threadIdx.x==0) sm[nc]=red[0]/(float)(HW*HW);
}

// ---------------- 4. SE MLP: sigmoid(gelu(s@se1)@se2) ----------------
__global__ void k_se(const float* __restrict__ sm, const float* __restrict__ se1,
                     const float* __restrict__ se2, float* __restrict__ sv){
    int n=blockIdx.x;
    __shared__ float sin_[D];
    __shared__ float hid[SEH];
    int t=threadIdx.x;            // 256 threads
    sin_[t]=sm[n*D+t];
    __syncthreads();
    if(t<SEH){
        float a=0.f;
        for(int c=0;c<D;c++) a+=sin_[c]*se1[c*SEH+t];
        hid[t]=gelu_f(a);
    }
    __syncthreads();
    float a=0.f;
    for(int j=0;j<SEH;j++) a+=hid[j]*se2[j*D+t];
    sv[n*D+t]=1.f/(1.f+expf(-a));
}

// ---------------- 5. pointwise conv (SE scale fused into A-tile) ----------------
// z[n,co,p] = sum_ci pw[co,ci]*sv[n,ci]*y[n,ci,p]
__global__ void k_pwconv(const float* __restrict__ pw, const float* __restrict__ y,
                         const float* __restrict__ sv, float* __restrict__ z, int P){
    __shared__ float As[16][65];
    __shared__ float Bs[16][65];
    int n=blockIdx.z;
    int co0=blockIdx.y*64;
    int p0 =blockIdx.x*64;
    int tid=threadIdx.x;
    int ty=tid>>4, tx=tid&15;
    const float* yb = y + (long)n*D*P;
    float acc[4][4]={};
    for(int k0=0;k0<D;k0+=16){
        #pragma unroll
        for(int l=0;l<4;l++){
            int e=tid+l*256; int kk=e&15, mm=e>>4;
            As[kk][mm]=pw[(co0+mm)*D + k0+kk]*sv[n*D+k0+kk];
        }
        #pragma unroll
        for(int l=0;l<4;l++){
            int e=tid+l*256; int nn=e&63, kk=e>>6;
            int p=p0+nn;
            Bs[kk][nn]=(p<P)? yb[(long)(k0+kk)*P+p] : 0.f;
        }
        __syncthreads();
        #pragma unroll
        for(int kk=0;kk<16;kk++){
            float a[4],b[4];
            #pragma unroll
            for(int i=0;i<4;i++) a[i]=As[kk][ty*4+i];
            #pragma unroll
            for(int j=0;j<4;j++) b[j]=Bs[kk][tx*4+j];
            #pragma unroll
            for(int i=0;i<4;i++)
                #pragma unroll
                for(int j=0;j<4;j++) acc[i][j]+=a[i]*b[j];
        }
        __syncthreads();
    }
    float* zb = z + (long)n*D*P;
    #pragma unroll
    for(int i=0;i<4;i++){
        int co=co0+ty*4+i;
        #pragma unroll
        for(int j=0;j<4;j++){
            int p=p0+tx*4+j;
            if(p<P) zb[(long)co*P+p]=acc[i][j];
        }
    }
}

// ---------------- 6. residual add + maxpool 3x3 s2 p1 ----------------
__global__ void k_respool(const float* __restrict__ xin, const float* __restrict__ z,
                          float* __restrict__ out, int Hin, int Hout){
    int o=blockIdx.x*blockDim.x+threadIdx.x;
    int total=NB*D*Hout*Hout;
    if(o>=total) return;
    int wo=o%Hout; int t=o/Hout;
    int ho=t%Hout; t/=Hout;       // t = n*D + c
    const float* xp = xin + (long)t*Hin*Hin;
    const float* zp = z   + (long)t*Hin*Hin;
    float mx=-INFINITY;
    #pragma unroll
    for(int kh=0;kh<3;kh++){
        int hh=2*ho-1+kh;
        if(hh<0||hh>=Hin) continue;
        #pragma unroll
        for(int kw=0;kw<3;kw++){
            int ww=2*wo-1+kw;
            if(ww<0||ww>=Hin) continue;
            float v=xp[hh*Hin+ww]+zp[hh*Hin+ww];
            mx=fmaxf(mx,v);
        }
    }
    out[o]=mx;
}

// ---------------- 7. global attention per (b, group) ----------------
// X[98][256] in smem; S=softmax(X X^T)*(1/16); out = S X
__global__ void k_gattn(){
    extern __shared__ float dsm[];
    float* X=dsm;              // 98*257
    float* S=dsm+98*257;       // 98*99
    int bg=blockIdx.x; int b=bg>>2, g=bg&3;
    int nx=g>>1, ny=g&1;
    int tid=threadIdx.x;
    for(int e=tid;e<NTOK*D;e+=256){
        int c=e&255, i=e>>8;
        int m=i/49, rr=i%49, w1=rr/7, w2=rr%7;
        int n=b*2+m;
        X[i*257+c]=g_xg2[(((long)n*D+c)*H3 + (nx*7+w1))*H3 + (ny*7+w2)];
    }
    __syncthreads();
    for(int p=tid;p<NTOK*NTOK;p+=256){
        int i=p/NTOK, j=p%NTOK;
        const float* xi=&X[i*257];
        const float* xj=&X[j*257];
        float a=0.f;
        #pragma unroll 8
        for(int k=0;k<D;k++) a+=xi[k]*xj[k];
        S[i*99+j]=a;
    }
    __syncthreads();
    int wd=tid>>5, lane=tid&31;
    for(int i=wd;i<NTOK;i+=8){
        float mx=-INFINITY;
        for(int j=lane;j<NTOK;j+=32) mx=fmaxf(mx,S[i*99+j]);
        for(int o=16;o>0;o>>=1) mx=fmaxf(mx,__shfl_xor_sync(0xffffffffu,mx,o));
        float sum=0.f;
        for(int j=lane;j<NTOK;j+=32){ float e2=expf(S[i*99+j]-mx); S[i*99+j]=e2; sum+=e2; }
        for(int o=16;o>0;o>>=1) sum+=__shfl_xor_sync(0xffffffffu,sum,o);
        float inv=0.0625f/sum;  // softmax * C^-0.5 (C=256)
        for(int j=lane;j<NTOK;j+=32) S[i*99+j]*=inv;
    }
    __syncthreads();
    for(int e=tid;e<NTOK*D;e+=256){
        int c=e&255, i=e>>8;
        float a=0.f;
        for(int j=0;j<NTOK;j++) a+=S[i*99+j]*X[j*257+c];
        g_gout[((long)bg*NTOK+i)*D+c]=a;
    }
}

// ---------------- 8. mean over 4 groups ----------------
__global__ void k_qmean(){
    int o=blockIdx.x*blockDim.x+threadIdx.x;
    if(o>=8*NTOK*D) return;
    int c=o&255; int t=o>>8; int i=t%NTOK; int b=t/NTOK;
    float a=0.f;
    for(int g=0;g<4;g++) a+=g_gout[(((long)(b*4+g)*NTOK)+i)*D+c];
    g_qglob[o]=a*0.25f;
}

// ---------------- 9. QKV GEMM (gathered A rows from x) ----------------
__global__ void k_gemm_qkv(const float* __restrict__ x, const float* __restrict__ Wm,
                           const float* __restrict__ bias){
    __shared__ float As[16][65];
    __shared__ float Bs[16][65];
    __shared__ long rowoff[64];
    int tid=threadIdx.x;
    int m0=blockIdx.y*64, n0=blockIdx.x*64;
    if(tid<64) rowoff[tid]=xrow_off(m0+tid);
    __syncthreads();
    float acc[4][4]={};
    int ty=tid>>4, tx=tid&15;
    for(int k0=0;k0<256;k0+=16){
        #pragma unroll
        for(int l=0;l<4;l++){
            int e=tid+l*256; int kk=e&15, mm=e>>4;
            As[kk][mm]=x[rowoff[mm]+k0+kk];
        }
        #pragma unroll
        for(int l=0;l<4;l++){
            int e=tid+l*256; int nn=e&63, kk=e>>6;
            Bs[kk][nn]=Wm[(k0+kk)*512 + n0+nn];
        }
        __syncthreads();
        #pragma unroll
        for(int kk=0;kk<16;kk++){
            float a[4],b[4];
            #pragma unroll
            for(int i=0;i<4;i++) a[i]=As[kk][ty*4+i];
            #pragma unroll
            for(int j=0;j<4;j++) b[j]=Bs[kk][tx*4+j];
            #pragma unroll
            for(int i=0;i<4;i++)
                #pragma unroll
                for(int j=0;j<4;j++) acc[i][j]+=a[i]*b[j];
        }
        __syncthreads();
    }
    #pragma unroll
    for(int i=0;i<4;i++){
        long r=m0+ty*4+i;
        #pragma unroll
        for(int j=0;j<4;j++){
            int n=n0+tx*4+j;
            g_kv[r*512+n]=acc[i][j]+bias[n];
        }
    }
}

// ---------------- 10. RPE bias gather ----------------
__global__ void k_bias(const float* __restrict__ rpe){
    int o=blockIdx.x*blockDim.x+threadIdx.x;
    if(o>=NH*NTOK*NTOK) return;
    int j=o%NTOK; int t=o/NTOK; int i=t%NTOK; int h=t/NTOK;
    int mi=i/49, ri=i%49, ai=ri/7, bi=ri%7;
    int mj=j/49, rj=j%49, aj=rj/7, bj=rj%7;
    int idx=(mi-mj+1)*169 + (ai-aj+6)*13 + (bi-bj+6);
    g_biasb[o]=rpe[idx*NH+h];
}

// ---------------- 11. window attention per (win, head) ----------------
__global__ void k_wattn(){
    extern __shared__ float dsm[];
    float* q=dsm;              // 98*33
    float* k=dsm+NTOK*33;
    float* v=dsm+2*NTOK*33;
    float* S=dsm+3*NTOK*33;    // 98*99
    int wh=blockIdx.x; int head=wh&7; int win=wh>>3;
    int b=win>>6;
    int tid=threadIdx.x;
    const float scale=0.17677669529663687f; // 32^-0.5
    for(int e=tid;e<NTOK*HD;e+=256){
        int i=e>>5, c=e&31;
        q[i*33+c]=g_qglob[((long)b*NTOK+i)*D + head*32+c]*scale;
        long kvb=((long)win*NTOK+i)*512 + head*32+c;
        k[i*33+c]=g_kv[kvb];
        v[i*33+c]=g_kv[kvb+256];
    }
    __syncthreads();
    const float* bs=&g_biasb[(long)head*NTOK*NTOK];
    for(int p=tid;p<NTOK*NTOK;p+=256){
        int i=p/NTOK, j=p%NTOK;
        float a=bs[p];
        const float* qi=&q[i*33];
        const float* kj=&k[j*33];
        #pragma unroll
        for(int c=0;c<HD;c++) a+=qi[c]*kj[c];
        S[i*99+j]=a;
    }
    __syncthreads();
    int wd=tid>>5, lane=tid&31;
    for(int i=wd;i<NTOK;i+=8){
        float mx=-INFINITY;
        for(int j=lane;j<NTOK;j+=32) mx=fmaxf(mx,S[i*99+j]);
        for(int o=16;o>0;o>>=1) mx=fmaxf(mx,__shfl_xor_sync(0xffffffffu,mx,o));
        float sum=0.f;
        for(int j=lane;j<NTOK;j+=32){ float e2=expf(S[i*99+j]-mx); S[i*99+j]=e2; sum+=e2; }
        for(int o=16;o>0;o>>=1) sum+=__shfl_xor_sync(0xffffffffu,sum,o);
        float inv=1.f/sum;
        for(int j=lane;j<NTOK;j+=32) S[i*99+j]*=inv;
    }
    __syncthreads();
    for(int e=tid;e<NTOK*HD;e+=256){
        int i=e>>5, c=e&31;
        float a=0.f;
        for(int j=0;j<NTOK;j++) a+=S[i*99+j]*v[j*33+c];
        g_aout[((long)win*NTOK+i)*D + head*32+c]=a;
    }
}

// ---------------- 12. to_out GEMM (scatter C rows to output layout) ----------------
__global__ void k_gemm_out(const float* __restrict__ Wm, float* __restrict__ outp){
    __shared__ float As[16][65];
    __shared__ float Bs[16][65];
    __shared__ long rowoff[64];
    int tid=threadIdx.x;
    int m0=blockIdx.y*64, n0=blockIdx.x*64;
    if(tid<64) rowoff[tid]=xrow_off(m0+tid);
    __syncthreads();
    float acc[4][4]={};
    int ty=tid>>4, tx=tid&15;
    for(int k0=0;k0<256;k0+=16){
        #pragma unroll
        for(int l=0;l<4;l++){
            int e=tid+l*256; int kk=e&15, mm=e>>4;
            As[kk][mm]=g_aout[(long)(m0+mm)*256 + k0+kk];
        }
        #pragma unroll
        for(int l=0;l<4;l++){
            int e=tid+l*256; int nn=e&63, kk=e>>6;
            Bs[kk][nn]=Wm[(k0+kk)*256 + n0+nn];
        }
        __syncthreads();
        #pragma unroll
        for(int kk=0;kk<16;kk++){
            float a[4],b[4];
            #pragma unroll
            for(int i=0;i<4;i++) a[i]=As[kk][ty*4+i];
            #pragma unroll
            for(int j=0;j<4;j++) b[j]=Bs[kk][tx*4+j];
            #pragma unroll
            for(int i=0;i<4;i++)
                #pragma unroll
                for(int j=0;j<4;j++) acc[i][j]+=a[i]*b[j];
        }
        __syncthreads();
    }
    #pragma unroll
    for(int i=0;i<4;i++){
        long ro=rowoff[ty*4+i];
        #pragma unroll
        for(int j=0;j<4;j++){
            int n=n0+tx*4+j;
            outp[ro+n]=acc[i][j];
        }
    }
}

// ---------------- host ----------------
extern "C" void kernel_launch(void* const* d_in, const int* in_sizes, int n_in,
                              void* d_out, int out_size){
    (void)in_sizes; (void)n_in; (void)out_size;
    const float* x       =(const float*)d_in[0];
    const float* qkv_w   =(const float*)d_in[1];
    const float* qkv_b   =(const float*)d_in[2];
    const float* to_out_w=(const float*)d_in[3];
    const float* rpe     =(const float*)d_in[4];
    const float* fe1_dw  =(const float*)d_in[5];
    const float* fe1_se1 =(const float*)d_in[6];
    const float* fe1_se2 =(const float*)d_in[7];
    const float* fe1_pw  =(const float*)d_in[8];
    const float* fe2_dw  =(const float*)d_in[9];
    const float* fe2_se1 =(const float*)d_in[10];
    const float* fe2_se2 =(const float*)d_in[11];
    const float* fe2_pw  =(const float*)d_in[12];
    float* outp=(float*)d_out;

    float *xg0,*yb,*zb,*xg1,*xg2,*smean,*svec;
    cudaGetSymbolAddress((void**)&xg0,  g_xg0);
    cudaGetSymbolAddress((void**)&yb,   g_y);
    cudaGetSymbolAddress((void**)&zb,   g_z);
    cudaGetSymbolAddress((void**)&xg1,  g_xg1);
    cudaGetSymbolAddress((void**)&xg2,  g_xg2);
    cudaGetSymbolAddress((void**)&smean,g_smean);
    cudaGetSymbolAddress((void**)&svec, g_svec);

    const int GATTN_SMEM=(98*257 + 98*99)*4;   // 139552 B
    const int WATTN_SMEM=(3*98*33 + 98*99)*4;  // 77616 B
    cudaFuncSetAttribute(k_gattn, cudaFuncAttributeMaxDynamicSharedMemorySize, GATTN_SMEM);
    cudaFuncSetAttribute(k_wattn, cudaFuncAttributeMaxDynamicSharedMemorySize, WATTN_SMEM);

    // rearrange
    k_rearrange<<<(NB*D*H1*H1+255)/256,256>>>(x);
    // FE1: 56 -> 28
    k_dwconv_gelu<<<(NB*D*H1*H1+255)/256,256>>>(xg0, fe1_dw, yb, H1);
    k_hwmean<<<NB*D,256>>>(yb, smean, H1);
    k_se<<<NB,256>>>(smean, fe1_se1, fe1_se2, svec);
    k_pwconv<<<dim3((H1*H1+63)/64,4,NB),256>>>(fe1_pw, yb, svec, zb, H1*H1);
    k_respool<<<(NB*D*H2*H2+255)/256,256>>>(xg0, zb, xg1, H1, H2);
    // FE2: 28 -> 14
    k_dwconv_gelu<<<(NB*D*H2*H2+255)/256,256>>>(xg1, fe2_dw, yb, H2);
    k_hwmean<<<NB*D,256>>>(yb, smean, H2);
    k_se<<<NB,256>>>(smean, fe2_se1, fe2_se2, svec);
    k_pwconv<<<dim3((H2*H2+63)/64,4,NB),256>>>(fe2_pw, yb, svec, zb, H2*H2);
    k_respool<<<(NB*D*H3*H3+255)/256,256>>>(xg1, zb, xg2, H2, H3);
    // global attention -> q_global
    k_gattn<<<32,256,GATTN_SMEM>>>();
    k_qmean<<<(8*NTOK*D+255)/256,256>>>();
    // window path
    k_gemm_qkv<<<dim3(8,MROWS/64),256>>>(x, qkv_w, qkv_b);
    k_bias<<<(NH*NTOK*NTOK+255)/256,256>>>(rpe);
    k_wattn<<<NWIN*NH,256,WATTN_SMEM>>>();
    k_gemm_out<<<dim3(4,MROWS/64),256>>>(to_out_w, outp);
}